// round 11
// baseline (speedup 1.0000x reference)
#include <cuda_runtime.h>
#include <math.h>

// AnomalyAttention: B=2, L=2048, H=8, E=64, band |i-j| <= 63.
// out = concat( V [B,L,H,E] f32 , series [B,H,L,L] f32 ).
// RT=64 tiles, 512 threads, 1 CTA/SM.
// Series row = [0,jbase) zeros (bulk) | [jbase,jbase+160) direct STG | rest zeros (bulk).
// GEMM2: warp PAIRS split by e-column -> 8 rows x 32 cols per warp, half the V smem traffic.

#define BN 2
#define HN 8
#define LN 2048
#define EN 64
#define RT 64          // rows per block
#define WROWS 192      // K window rows
#define KSTR 68        // Q/K smem row stride (68%32=4 -> LDS.128 conflict-free)
#define VTSTR 196      // VT row stride (192 data + 4 pad; 196%32=4 -> conflict-free)
#define PSSTR 160      // Ps row stride
#define ZB_FLOATS 2048 // zero source (max segment 1980 floats)
#define SCALE_L2E 0.18033688011112042f   // 0.125 * log2(e)

typedef unsigned long long u64;

__device__ __forceinline__ u64 fma2(u64 a, u64 b, u64 c) {
    u64 d;
    asm("fma.rn.f32x2 %0, %1, %2, %3;" : "=l"(d) : "l"(a), "l"(b), "l"(c));
    return d;
}
__device__ __forceinline__ float2 unpack2(u64 v) {
    float2 r;
    asm("mov.b64 {%0, %1}, %2;" : "=f"(r.x), "=f"(r.y) : "l"(v));
    return r;
}
__device__ __forceinline__ float ex2f(float x) {
    float y;
    asm("ex2.approx.ftz.f32 %0, %1;" : "=f"(y) : "f"(x));
    return y;
}
__device__ __forceinline__ unsigned smem_u32(const void* p) {
    return (unsigned)__cvta_generic_to_shared(p);
}
__device__ __forceinline__ void bulk_store(void* dst, unsigned src_smem, unsigned bytes) {
    asm volatile("cp.async.bulk.global.shared::cta.bulk_group [%0], [%1], %2;"
                 :: "l"(dst), "r"(src_smem), "r"(bytes) : "memory");
}
__device__ __forceinline__ void cp16(float* dst_smem, const float* src) {
    asm volatile("cp.async.cg.shared.global [%0], [%1], 16;"
                 :: "r"(smem_u32(dst_smem)), "l"(src) : "memory");
}

__global__ __launch_bounds__(512, 1)
void anomaly_attn_kernel(const float* __restrict__ Q,
                         const float* __restrict__ K,
                         const float* __restrict__ V,
                         float* __restrict__ out)
{
    extern __shared__ float sm[];
    float* Qs  = sm;                        // RT    * KSTR
    float* Ks  = Qs + RT * KSTR;            // WROWS * KSTR
    float* VT  = Ks + WROWS * KSTR;         // EN * VTSTR
    float* Ps  = VT + EN * VTSTR;           // RT * PSSTR (raw p, cols rel. per-warp jbase)
    float* Zb  = Ps + RT * PSSTR;           // ZB_FLOATS zeros
    float* Rin = Zb + ZB_FLOATS;            // RT rinv values

    const int bid = blockIdx.x;
    const int t   = bid & 31;
    const int h   = (bid >> 5) & 7;
    const int b   = bid >> 8;
    const int i0  = t * RT;
    const int wbase = min(max(i0 - 64, 0), LN - WROWS);

    const int tid  = threadIdx.x;
    const int lane = tid & 31;
    const int w    = tid >> 5;             // 16 warps x 4 rows (GEMM1/softmax)
    const int ga   = 4 * w;
    const int gia  = i0 + ga;

    float* series = out + (size_t)BN * LN * HN * EN;
    const size_t growbase = (size_t)((b * HN + h) * LN);

    // ---- cp.async fill of Q and K ----
    {
        const int e4 = (tid & 15) * 4;
        const int r0 = tid >> 4;           // 0..31
#pragma unroll
        for (int r = r0; r < RT; r += 32)
            cp16(Qs + r * KSTR + e4, &Q[(((size_t)b * LN + (i0 + r)) * HN + h) * EN + e4]);
#pragma unroll
        for (int r = r0; r < WROWS; r += 32)
            cp16(Ks + r * KSTR + e4, &K[(((size_t)b * LN + (wbase + r)) * HN + h) * EN + e4]);
        asm volatile("cp.async.commit_group;" ::: "memory");
    }

    // ---- VT[e][col] transpose gather (overlaps cp.async drain) + Zb ----
    {
        const int e  = tid & 63;
        const int jg = (tid >> 6) * 4;     // 0..28
#pragma unroll
        for (int j4 = jg; j4 < WROWS; j4 += 32) {
            const float* vp = &V[(((size_t)b * LN + (wbase + j4)) * HN + h) * EN + e];
            float4 v;
            v.x = vp[0];
            v.y = vp[HN * EN];
            v.z = vp[2 * HN * EN];
            v.w = vp[3 * HN * EN];
            *(float4*)(VT + e * VTSTR + j4) = v;
        }
        *(float4*)(Zb + tid * 4) = make_float4(0.f, 0.f, 0.f, 0.f);
        if (tid < EN)
            *(float4*)(VT + tid * VTSTR + WROWS) = make_float4(0.f, 0.f, 0.f, 0.f);
    }
    asm volatile("cp.async.wait_group 0;" ::: "memory");
    __syncthreads();

    // ---- per-warp geometry: aligned 160-col store window ----
    const int jbase = max(0, gia - 63) & ~3;            // 16B aligned
    const int off   = jbase - wbase;
    const int spanw = min(LN - 1, gia + 66) - jbase;    // <= 133

    // ---- issue zero-segment bulk stores (drain under all compute) ----
    if (lane == 0) {
        asm volatile("fence.proxy.async.shared::cta;" ::: "memory");
        const unsigned zb_addr = smem_u32(Zb);
        const unsigned lbytes = (unsigned)jbase * 4u;
        const int rlen = LN - (jbase + 160);
#pragma unroll
        for (int r = 0; r < 4; r++) {
            float* rowp = series + (growbase + (gia + r)) * (size_t)LN;
            if (lbytes) bulk_store(rowp, zb_addr, lbytes);
            if (rlen > 0) bulk_store(rowp + jbase + 160, zb_addr, (unsigned)rlen * 4u);
        }
    }

    // ---- GEMM1: scores[4][5], LDS.128 + f32x2 ----
    u64 acc[4][5];
#pragma unroll
    for (int r = 0; r < 4; r++)
#pragma unroll
        for (int s = 0; s < 5; s++) acc[r][s] = 0ull;

    const ulonglong2* kp[5];
#pragma unroll
    for (int s = 0; s < 5; s++) {
        const int row = min(off + lane + 32 * s, WROWS - 1);  // clamped lanes masked later
        kp[s] = (const ulonglong2*)(Ks + row * KSTR);
    }
    const ulonglong2* qp0 = (const ulonglong2*)(Qs + (ga + 0) * KSTR);
    const ulonglong2* qp1 = (const ulonglong2*)(Qs + (ga + 1) * KSTR);
    const ulonglong2* qp2 = (const ulonglong2*)(Qs + (ga + 2) * KSTR);
    const ulonglong2* qp3 = (const ulonglong2*)(Qs + (ga + 3) * KSTR);

#pragma unroll 4
    for (int e4 = 0; e4 < EN / 4; e4++) {
        const ulonglong2 q0 = qp0[e4], q1 = qp1[e4], q2 = qp2[e4], q3 = qp3[e4];
#pragma unroll
        for (int s = 0; s < 5; s++) {
            const ulonglong2 kk = kp[s][e4];
            acc[0][s] = fma2(q0.x, kk.x, acc[0][s]);
            acc[0][s] = fma2(q0.y, kk.y, acc[0][s]);
            acc[1][s] = fma2(q1.x, kk.x, acc[1][s]);
            acc[1][s] = fma2(q1.y, kk.y, acc[1][s]);
            acc[2][s] = fma2(q2.x, kk.x, acc[2][s]);
            acc[2][s] = fma2(q2.y, kk.y, acc[2][s]);
            acc[3][s] = fma2(q3.x, kk.x, acc[3][s]);
            acc[3][s] = fma2(q3.y, kk.y, acc[3][s]);
        }
    }

    // ---- pass 1: raw p -> Ps (all 160 window cols; zeros where masked), row sums ----
    float sum[4] = { 0.f, 0.f, 0.f, 0.f };
#pragma unroll
    for (int s = 0; s < 5; s++) {
        const int jj = lane + 32 * s;
        const int j  = jbase + jj;
#pragma unroll
        for (int r = 0; r < 4; r++) {
            const int gi = gia + r;
            const bool c = (jj <= spanw) && ((unsigned)(j - gi + 63) <= 126u);
            float p = 0.0f;
            if (c) {
                const float2 a = unpack2(acc[r][s]);
                p = ex2f((a.x + a.y) * SCALE_L2E);
                sum[r] += p;
            }
            Ps[(ga + r) * PSSTR + jj] = p;
        }
    }
#pragma unroll
    for (int o = 16; o > 0; o >>= 1)
#pragma unroll
        for (int r = 0; r < 4; r++)
            sum[r] += __shfl_xor_sync(0xffffffffu, sum[r], o);

    float rinv[4];
#pragma unroll
    for (int r = 0; r < 4; r++) rinv[r] = 1.0f / sum[r];

    if (lane == 0) {
        Rin[ga + 0] = rinv[0];
        Rin[ga + 1] = rinv[1];
        Rin[ga + 2] = rinv[2];
        Rin[ga + 3] = rinv[3];
    }

    // ---- series in-band: direct coalesced STG.32 (own-lane Ps readback) ----
#pragma unroll
    for (int r = 0; r < 4; r++) {
        const float rv = rinv[r];
        float* rowp = series + (growbase + (gia + r)) * (size_t)LN;
        const float* prow = Ps + (ga + r) * PSSTR;
#pragma unroll
        for (int s = 0; s < 5; s++) {
            const int jj = lane + 32 * s;
            const int j  = jbase + jj;
            if (j < LN) __stcs(rowp + j, prow[jj] * rv);
        }
    }

    // ---- all Ps rows + Rin visible block-wide (pairs read each other's rows) ----
    __syncthreads();

    // ---- GEMM2 (warp-pair e-split): 8 rows x 32 e-cols per warp ----
    const int pga = 8 * (w >> 1);                       // pair local row base
    const int gpa = i0 + pga;
    const int jbA = max(0, gpa - 63) & ~3;              // even warp's jbase
    const int jbB = max(0, gpa + 4 - 63) & ~3;          // odd warp's jbase
    const int dB  = jbB - jbA;                          // 0 or 4
    const int spanP = min(LN - 1, gpa + 70) - jbA;      // <= 137
    const int offP  = jbA - wbase;
    const int ec    = 32 * (w & 1) + lane;              // this warp's e column

    u64 a[8];
#pragma unroll
    for (int r = 0; r < 8; r++) a[r] = 0ull;

    const int niter = (spanP >> 2) + 1;                 // <= 35
    const float* vt = VT + ec * VTSTR + offP;
    const float* psA = Ps + pga * PSSTR;
    const float* psB = Ps + (pga + 4) * PSSTR - dB;
#pragma unroll 2
    for (int it = 0; it < niter; it++) {
        const int jj = 4 * it;
        const ulonglong2 v = *(const ulonglong2*)(vt + jj);
#pragma unroll
        for (int rr = 0; rr < 4; rr++) {
            const ulonglong2 pr = *(const ulonglong2*)(psA + rr * PSSTR + jj);
            a[rr] = fma2(pr.x, v.x, a[rr]);
            a[rr] = fma2(pr.y, v.y, a[rr]);
        }
        if (jj >= dB) {
#pragma unroll
            for (int rr = 0; rr < 4; rr++) {
                const ulonglong2 pr = *(const ulonglong2*)(psB + rr * PSSTR + jj);
                a[4 + rr] = fma2(pr.x, v.x, a[4 + rr]);
                a[4 + rr] = fma2(pr.y, v.y, a[4 + rr]);
            }
        }
    }
#pragma unroll
    for (int rr = 0; rr < 8; rr++) {
        const int gi = gpa + rr;
        const float rv = Rin[pga + rr];
        const size_t o = (((size_t)b * LN + gi) * HN + h) * EN;
        const float2 x = unpack2(a[rr]);
        out[o + ec] = (x.x + x.y) * rv;
    }

    // ---- drain async zero stores ----
    if (lane == 0) {
        asm volatile("cp.async.bulk.commit_group;" ::: "memory");
        asm volatile("cp.async.bulk.wait_group 0;" ::: "memory");
    }
}

extern "C" void kernel_launch(void* const* d_in, const int* in_sizes, int n_in,
                              void* d_out, int out_size) {
    const float* Q = (const float*)d_in[0];
    const float* K = (const float*)d_in[1];
    const float* V = (const float*)d_in[2];
    float* out = (float*)d_out;

    const int smem_bytes =
        (RT * KSTR + WROWS * KSTR + EN * VTSTR + RT * PSSTR + ZB_FLOATS + RT) * (int)sizeof(float);
    cudaFuncSetAttribute(anomaly_attn_kernel,
                         cudaFuncAttributeMaxDynamicSharedMemorySize, smem_bytes);

    dim3 grid(BN * HN * (LN / RT));   // 512 blocks
    dim3 block(512);
    anomaly_attn_kernel<<<grid, block, smem_bytes>>>(Q, K, V, out);
}

// round 12
// speedup vs baseline: 1.0289x; 1.0289x over previous
#include <cuda_runtime.h>
#include <math.h>

// AnomalyAttention: B=2, L=2048, H=8, E=64, band |i-j| <= 63.
// out = concat( V [B,L,H,E] f32 , series [B,H,L,L] f32 ).
// RT=64 tiles, 512 threads, 1 CTA/SM.
// Fill: cp.async Q,K (group A) + V staging (group B); GEMM1 starts after A only.
// V transposed smem->smem into VT (aliases dead Qs/Ks) after GEMM1.
// Series row = [0,jbase) zeros (bulk) | [jbase,jbase+160) float4 STG | rest zeros (bulk).

#define BN 2
#define HN 8
#define LN 2048
#define EN 64
#define RT 64          // rows per block
#define WROWS 192      // K/V window rows
#define KSTR 68        // Q/K/Vs smem row stride (68%32=4 -> conflict-free LDS.128)
#define VTSTR 196      // VT row stride (192 data + 4 pad; 196%32=4 -> conflict-free)
#define PSSTR 160      // Ps row stride
#define ZB_FLOATS 2048 // zero source (max segment 1980 floats)
#define SCALE_L2E 0.18033688011112042f   // 0.125 * log2(e)

typedef unsigned long long u64;

__device__ __forceinline__ u64 fma2(u64 a, u64 b, u64 c) {
    u64 d;
    asm("fma.rn.f32x2 %0, %1, %2, %3;" : "=l"(d) : "l"(a), "l"(b), "l"(c));
    return d;
}
__device__ __forceinline__ float2 unpack2(u64 v) {
    float2 r;
    asm("mov.b64 {%0, %1}, %2;" : "=f"(r.x), "=f"(r.y) : "l"(v));
    return r;
}
__device__ __forceinline__ float ex2f(float x) {
    float y;
    asm("ex2.approx.ftz.f32 %0, %1;" : "=f"(y) : "f"(x));
    return y;
}
__device__ __forceinline__ unsigned smem_u32(const void* p) {
    return (unsigned)__cvta_generic_to_shared(p);
}
__device__ __forceinline__ void bulk_store(void* dst, unsigned src_smem, unsigned bytes) {
    asm volatile("cp.async.bulk.global.shared::cta.bulk_group [%0], [%1], %2;"
                 :: "l"(dst), "r"(src_smem), "r"(bytes) : "memory");
}
__device__ __forceinline__ void cp16(float* dst_smem, const float* src) {
    asm volatile("cp.async.cg.shared.global [%0], [%1], 16;"
                 :: "r"(smem_u32(dst_smem)), "l"(src) : "memory");
}

__global__ __launch_bounds__(512, 1)
void anomaly_attn_kernel(const float* __restrict__ Q,
                         const float* __restrict__ K,
                         const float* __restrict__ V,
                         float* __restrict__ out)
{
    extern __shared__ float sm[];
    float* Qs  = sm;                        // RT    * KSTR = 4352
    float* Ks  = Qs + RT * KSTR;            // WROWS * KSTR = 13056
    float* Vs  = Ks + WROWS * KSTR;         // WROWS * KSTR = 13056 (V staging, row-major)
    float* Ps  = Vs + WROWS * KSTR;         // RT * PSSTR   = 10240 (raw p, window cols)
    float* Zb  = Ps + RT * PSSTR;           // 2048 zeros
    float* Rin = Zb + ZB_FLOATS;            // RT rinv
    float* VT  = Qs;                        // EN * VTSTR = 12544, ALIASES Qs/Ks (dead post-GEMM1)

    const int bid = blockIdx.x;
    const int t   = bid & 31;
    const int h   = (bid >> 5) & 7;
    const int b   = bid >> 8;
    const int i0  = t * RT;
    const int wbase = min(max(i0 - 64, 0), LN - WROWS);

    const int tid  = threadIdx.x;
    const int lane = tid & 31;
    const int w    = tid >> 5;             // 16 warps x 4 rows
    const int ga   = 4 * w;
    const int gia  = i0 + ga;

    float* series = out + (size_t)BN * LN * HN * EN;
    const size_t growbase = (size_t)((b * HN + h) * LN);

    // ---- cp.async fills: group A = Q,K ; group B = V ----
    {
        const int e4 = (tid & 15) * 4;
        const int r0 = tid >> 4;           // 0..31
#pragma unroll
        for (int r = r0; r < RT; r += 32)
            cp16(Qs + r * KSTR + e4, &Q[(((size_t)b * LN + (i0 + r)) * HN + h) * EN + e4]);
#pragma unroll
        for (int r = r0; r < WROWS; r += 32)
            cp16(Ks + r * KSTR + e4, &K[(((size_t)b * LN + (wbase + r)) * HN + h) * EN + e4]);
        asm volatile("cp.async.commit_group;" ::: "memory");
#pragma unroll
        for (int r = r0; r < WROWS; r += 32)
            cp16(Vs + r * KSTR + e4, &V[(((size_t)b * LN + (wbase + r)) * HN + h) * EN + e4]);
        asm volatile("cp.async.commit_group;" ::: "memory");

        *(float4*)(Zb + tid * 4) = make_float4(0.f, 0.f, 0.f, 0.f);
    }
    asm volatile("cp.async.wait_group 1;" ::: "memory");   // Q,K only
    __syncthreads();

    // ---- per-warp geometry: aligned 160-col store window ----
    const int jbase = max(0, gia - 63) & ~3;            // 16B aligned
    const int off   = jbase - wbase;
    const int spanw = min(LN - 1, gia + 66) - jbase;    // <= 133

    // ---- issue zero-segment bulk stores (drain under all compute) ----
    if (lane == 0) {
        asm volatile("fence.proxy.async.shared::cta;" ::: "memory");
        const unsigned zb_addr = smem_u32(Zb);
        const unsigned lbytes = (unsigned)jbase * 4u;
        const int rlen = LN - (jbase + 160);
#pragma unroll
        for (int r = 0; r < 4; r++) {
            float* rowp = series + (growbase + (gia + r)) * (size_t)LN;
            if (lbytes) bulk_store(rowp, zb_addr, lbytes);
            if (rlen > 0) bulk_store(rowp + jbase + 160, zb_addr, (unsigned)rlen * 4u);
        }
    }

    // ---- GEMM1: scores[4][5], LDS.128 + f32x2 ----
    u64 acc[4][5];
#pragma unroll
    for (int r = 0; r < 4; r++)
#pragma unroll
        for (int s = 0; s < 5; s++) acc[r][s] = 0ull;

    const ulonglong2* kp[5];
#pragma unroll
    for (int s = 0; s < 5; s++) {
        const int row = min(off + lane + 32 * s, WROWS - 1);  // clamped lanes masked later
        kp[s] = (const ulonglong2*)(Ks + row * KSTR);
    }
    const ulonglong2* qp0 = (const ulonglong2*)(Qs + (ga + 0) * KSTR);
    const ulonglong2* qp1 = (const ulonglong2*)(Qs + (ga + 1) * KSTR);
    const ulonglong2* qp2 = (const ulonglong2*)(Qs + (ga + 2) * KSTR);
    const ulonglong2* qp3 = (const ulonglong2*)(Qs + (ga + 3) * KSTR);

#pragma unroll 4
    for (int e4 = 0; e4 < EN / 4; e4++) {
        const ulonglong2 q0 = qp0[e4], q1 = qp1[e4], q2 = qp2[e4], q3 = qp3[e4];
#pragma unroll
        for (int s = 0; s < 5; s++) {
            const ulonglong2 kk = kp[s][e4];
            acc[0][s] = fma2(q0.x, kk.x, acc[0][s]);
            acc[0][s] = fma2(q0.y, kk.y, acc[0][s]);
            acc[1][s] = fma2(q1.x, kk.x, acc[1][s]);
            acc[1][s] = fma2(q1.y, kk.y, acc[1][s]);
            acc[2][s] = fma2(q2.x, kk.x, acc[2][s]);
            acc[2][s] = fma2(q2.y, kk.y, acc[2][s]);
            acc[3][s] = fma2(q3.x, kk.x, acc[3][s]);
            acc[3][s] = fma2(q3.y, kk.y, acc[3][s]);
        }
    }

    // ---- pass 1: raw p -> Ps (all 160 window cols; zeros where masked), row sums ----
    float sum[4] = { 0.f, 0.f, 0.f, 0.f };
#pragma unroll
    for (int s = 0; s < 5; s++) {
        const int jj = lane + 32 * s;
        const int j  = jbase + jj;
#pragma unroll
        for (int r = 0; r < 4; r++) {
            const int gi = gia + r;
            const bool c = (jj <= spanw) && ((unsigned)(j - gi + 63) <= 126u);
            float p = 0.0f;
            if (c) {
                const float2 a = unpack2(acc[r][s]);
                p = ex2f((a.x + a.y) * SCALE_L2E);
                sum[r] += p;
            }
            Ps[(ga + r) * PSSTR + jj] = p;
        }
    }
#pragma unroll
    for (int o = 16; o > 0; o >>= 1)
#pragma unroll
        for (int r = 0; r < 4; r++)
            sum[r] += __shfl_xor_sync(0xffffffffu, sum[r], o);

    float rinv[4];
#pragma unroll
    for (int r = 0; r < 4; r++) rinv[r] = 1.0f / sum[r];
    if (lane == 0) {
        Rin[ga + 0] = rinv[0];
        Rin[ga + 1] = rinv[1];
        Rin[ga + 2] = rinv[2];
        Rin[ga + 3] = rinv[3];
    }

    // ---- V staged (group B) + Qs/Ks dead -> transpose Vs into VT (aliased) ----
    asm volatile("cp.async.wait_group 0;" ::: "memory");
    __syncthreads();   // Vs complete block-wide; Qs/Ks reads done; Ps/Rin visible

    {
        const int e  = tid & 63;
        const int jg = (tid >> 6) * 4;     // 0..28
#pragma unroll
        for (int j4 = jg; j4 < WROWS; j4 += 32) {
            float4 v;
            v.x = Vs[(j4 + 0) * KSTR + e];
            v.y = Vs[(j4 + 1) * KSTR + e];
            v.z = Vs[(j4 + 2) * KSTR + e];
            v.w = Vs[(j4 + 3) * KSTR + e];
            *(float4*)(VT + e * VTSTR + j4) = v;
        }
        if (tid < EN)   // zero pad cols 192..195 (GEMM2 tail)
            *(float4*)(VT + tid * VTSTR + WROWS) = make_float4(0.f, 0.f, 0.f, 0.f);
    }
    __syncthreads();   // VT visible block-wide

    // ---- series in-band: float4 readback of Ps, scale, STG.128 ----
    {
        const float4* psw = (const float4*)(Ps + ga * PSSTR);    // 160 float4 (4 rows x 40)
        float* rowbase = series + (growbase + gia) * (size_t)LN + jbase;
#pragma unroll
        for (int k = 0; k < 5; k++) {
            const int idx = lane + 32 * k;       // 0..159
            const int r   = idx / 40;
            const int c   = idx - 40 * r;        // float4 col within row
            const int j4  = jbase + 4 * c;
            if (j4 < LN) {
                const float rv = Rin[ga + r];
                float4 v = psw[idx];
                v.x *= rv; v.y *= rv; v.z *= rv; v.w *= rv;
                __stcs((float4*)(rowbase + (size_t)r * LN + 4 * c), v);
            }
        }
    }

    // ---- GEMM2: V_out[4][64] over window cols ----
    u64 a0[4], a1[4];
#pragma unroll
    for (int r = 0; r < 4; r++) { a0[r] = 0ull; a1[r] = 0ull; }

    const int niter = (spanw >> 2) + 1;                 // <= 34
    const float* vt0 = VT + lane * VTSTR + off;
    const float* vt1 = VT + (lane + 32) * VTSTR + off;
#pragma unroll 4
    for (int it = 0; it < niter; it++) {
        const int jj = 4 * it;
        const ulonglong2 v0 = *(const ulonglong2*)(vt0 + jj);
        const ulonglong2 v1 = *(const ulonglong2*)(vt1 + jj);
#pragma unroll
        for (int r = 0; r < 4; r++) {
            const ulonglong2 pr = *(const ulonglong2*)(Ps + (ga + r) * PSSTR + jj);
            a0[r] = fma2(pr.x, v0.x, a0[r]);
            a0[r] = fma2(pr.y, v0.y, a0[r]);
            a1[r] = fma2(pr.x, v1.x, a1[r]);
            a1[r] = fma2(pr.y, v1.y, a1[r]);
        }
    }
#pragma unroll
    for (int r = 0; r < 4; r++) {
        const int gi = gia + r;
        const size_t o = (((size_t)b * LN + gi) * HN + h) * EN;
        const float2 x0 = unpack2(a0[r]);
        const float2 x1 = unpack2(a1[r]);
        out[o + lane]      = (x0.x + x0.y) * rinv[r];
        out[o + 32 + lane] = (x1.x + x1.y) * rinv[r];
    }

    // ---- drain async zero stores ----
    if (lane == 0) {
        asm volatile("cp.async.bulk.commit_group;" ::: "memory");
        asm volatile("cp.async.bulk.wait_group 0;" ::: "memory");
    }
}

extern "C" void kernel_launch(void* const* d_in, const int* in_sizes, int n_in,
                              void* d_out, int out_size) {
    const float* Q = (const float*)d_in[0];
    const float* K = (const float*)d_in[1];
    const float* V = (const float*)d_in[2];
    float* out = (float*)d_out;

    const int smem_bytes =
        (RT * KSTR + 2 * WROWS * KSTR + RT * PSSTR + ZB_FLOATS + RT) * (int)sizeof(float);
    cudaFuncSetAttribute(anomaly_attn_kernel,
                         cudaFuncAttributeMaxDynamicSharedMemorySize, smem_bytes);

    dim3 grid(BN * HN * (LN / RT));   // 512 blocks
    dim3 block(512);
    anomaly_attn_kernel<<<grid, block, smem_bytes>>>(Q, K, V, out);
}